// round 12
// baseline (speedup 1.0000x reference)
#include <cuda_runtime.h>
#include <cuda_fp16.h>
#include <math.h>

// ---------------------------------------------------------------------------
// N=100000, F_in=128, F_hid=64, F_out=40, E=1600000 (+N self loops).
// h1 / h2 stored fp16; fp32 accumulation. CSR: 2 cooperative kernels.
// ---------------------------------------------------------------------------
#define MAXN 100000
#define MAXE 1700096

__device__ __half g_h1h[(size_t)MAXN * 64];
__device__ float  g_h1r[(size_t)MAXN * 64];
__device__ __half g_h2h[(size_t)MAXN * 40];
__device__ float  g_as[MAXN];
__device__ float  g_ad[MAXN];
__device__ int    g_cnt[MAXN];
__device__ int    g_off[MAXN + 1];
__device__ int    g_srcs[MAXE];
__device__ int    g_rank[MAXE];
__device__ int    g_partials[128];
__device__ int    g_bars[3];        // barrier counters (memset to 0 pre-launch)
__device__ int    g_is64;

// ---------------------------------------------------------------------------
// CSR stage A (148 blocks x 1024, co-resident): zero cnt, detect dtype,
// grid barrier, then histogram dsts recording per-edge rank.
// ---------------------------------------------------------------------------
__global__ void csr_a_kernel(const unsigned int* __restrict__ w,
                             int* __restrict__ cnt, int* __restrict__ rank,
                             int* flag, int* bars, int n, long long E) {
    long long gid = (long long)blockIdx.x * blockDim.x + threadIdx.x;
    long long gsz = (long long)gridDim.x * blockDim.x;
    for (long long j = gid; j < n; j += gsz) cnt[j] = 0;
    if (blockIdx.x == 0) {
        __shared__ int any;
        if (threadIdx.x == 0) any = 0;
        __syncthreads();
        for (int k = threadIdx.x; k < 1024; k += blockDim.x)
            if (w[2 * k + 1] != 0u) atomicOr(&any, 1);
        __syncthreads();
        if (threadIdx.x == 0) *flag = any ? 0 : 1;  // 1 => int64
    }
    // grid barrier
    __threadfence();
    __syncthreads();
    if (threadIdx.x == 0) {
        atomicAdd(&bars[0], 1);
        while (atomicAdd(&bars[0], 0) < gridDim.x) {}
    }
    __syncthreads();

    int is64 = *(volatile int*)flag;
    for (long long i = gid; i < E; i += gsz) {
        int d = is64 ? (int)((const uint2*)w)[E + i].x : (int)w[E + i];
        rank[i] = atomicAdd(&cnt[d], 1);
    }
}

// ---------------------------------------------------------------------------
// CSR stage B (98 blocks x 1024, co-resident): exclusive scan of (cnt+1)
// -> off (two grid barriers), then atomic-free fill of srcs via ranks.
// ---------------------------------------------------------------------------
__global__ void csr_b_kernel(const unsigned int* __restrict__ w,
                             const int* __restrict__ cnt,
                             const int* __restrict__ rank,
                             int* __restrict__ off, int* __restrict__ srcs,
                             int* __restrict__ partials, int* bars,
                             const int* __restrict__ flag,
                             int n, long long E, long long T) {
    __shared__ int sm[1024];
    __shared__ int pf[128];
    int tid = threadIdx.x, b = blockIdx.x;
    int i = b * 1024 + tid;
    int v = (i < n) ? cnt[i] + 1 : 0;   // +1 = self loop
    sm[tid] = v;
    __syncthreads();
    #pragma unroll
    for (int o = 1; o < 1024; o <<= 1) {
        int t = (tid >= o) ? sm[tid - o] : 0;
        __syncthreads();
        sm[tid] += t;
        __syncthreads();
    }
    int incl = sm[tid];

    if (tid == 0) {
        partials[b] = sm[1023];
        __threadfence();
        atomicAdd(&bars[1], 1);
        while (atomicAdd(&bars[1], 0) < gridDim.x) {}
    }
    __syncthreads();

    pf[tid & 127] = 0;
    __syncthreads();
    if (tid < 128) pf[tid] = (tid < b) ? partials[tid] : 0;
    __syncthreads();
    #pragma unroll
    for (int o = 64; o; o >>= 1) {
        if (tid < o) pf[tid] += pf[tid + o];
        __syncthreads();
    }
    int prefix = pf[0];

    if (i < n) off[i] = prefix + incl - v;
    if (i == 0) off[n] = (int)T;

    // grid barrier: all off[] visible before fill reads arbitrary entries
    __threadfence();
    __syncthreads();
    if (tid == 0) {
        atomicAdd(&bars[2], 1);
        while (atomicAdd(&bars[2], 0) < gridDim.x) {}
    }
    __syncthreads();

    int is64 = *(volatile int*)flag;
    long long gid = (long long)b * blockDim.x + tid;
    long long gsz = (long long)gridDim.x * blockDim.x;
    for (long long t = gid; t < T; t += gsz) {
        if (t < E) {
            int s, d;
            if (is64) {
                const uint2* w2 = (const uint2*)w;
                s = (int)w2[t].x;
                d = (int)w2[E + t].x;
            } else {
                s = (int)w[t];
                d = (int)w[E + t];
            }
            srcs[off[d] + rank[t]] = s;
        } else {
            int d = (int)(t - E);
            srcs[off[d] + cnt[d]] = d;
        }
    }
}

// ---------------------------------------------------------------------------
// GEMM1: h = x @ W (K=128, C=64), fp32 accumulation, fp16 output rows.
// Alpha dots fused into epilogue.
// ---------------------------------------------------------------------------
__global__ void gemm1_kernel(const float* __restrict__ x,
                             const float* __restrict__ W,
                             const float* __restrict__ asv,
                             const float* __restrict__ adv,
                             __half* __restrict__ h,
                             float* __restrict__ as_, float* __restrict__ ad_,
                             int Nn) {
    __shared__ float Xs[128 * 32];
    __shared__ float Ws[32 * 64];
    int tid = threadIdx.x;
    int row0 = blockIdx.x * 128;
    int rt = tid >> 3;
    int ct = tid & 7;
    int r0 = rt * 8;
    int kx = (rt & 3) << 3;

    unsigned long long acc[8][4];
    #pragma unroll
    for (int i = 0; i < 8; i++)
        #pragma unroll
        for (int j = 0; j < 4; j++) acc[i][j] = 0ull;

    const float4* x4 = (const float4*)x;

    for (int kc = 0; kc < 4; kc++) {
        const float4* W4 = (const float4*)(W + kc * 32 * 64);
        #pragma unroll
        for (int i = tid; i < 512; i += 128) ((float4*)Ws)[i] = W4[i];
        #pragma unroll
        for (int i = tid; i < 1024; i += 128) {
            int row = i >> 3;
            int c4  = i & 7;
            int gr = row0 + row;
            float4 v = (gr < Nn) ? x4[(size_t)gr * 32 + kc * 8 + c4]
                                 : make_float4(0.f, 0.f, 0.f, 0.f);
            int col = (c4 * 4) ^ (((row >> 3) & 3) << 3);
            *(float4*)&Xs[row * 32 + col] = v;
        }
        __syncthreads();

        #pragma unroll
        for (int k = 0; k < 32; k++) {
            longlong2 w0 = *(const longlong2*)&Ws[k * 64 + ct * 8];
            longlong2 w1 = *(const longlong2*)&Ws[k * 64 + ct * 8 + 4];
            #pragma unroll
            for (int i = 0; i < 8; i++) {
                float xv = Xs[(r0 + i) * 32 + (k ^ kx)];
                unsigned long long xx;
                asm("mov.b64 %0, {%1, %1};" : "=l"(xx) : "r"(__float_as_uint(xv)));
                asm("fma.rn.f32x2 %0, %1, %2, %0;" : "+l"(acc[i][0]) : "l"(xx), "l"((unsigned long long)w0.x));
                asm("fma.rn.f32x2 %0, %1, %2, %0;" : "+l"(acc[i][1]) : "l"(xx), "l"((unsigned long long)w0.y));
                asm("fma.rn.f32x2 %0, %1, %2, %0;" : "+l"(acc[i][2]) : "l"(xx), "l"((unsigned long long)w1.x));
                asm("fma.rn.f32x2 %0, %1, %2, %0;" : "+l"(acc[i][3]) : "l"(xx), "l"((unsigned long long)w1.y));
            }
        }
        __syncthreads();
    }

    const float4* as4 = (const float4*)asv;
    const float4* ad4 = (const float4*)adv;
    float4 sa0 = as4[ct * 2], sa1 = as4[ct * 2 + 1];
    float4 da0 = ad4[ct * 2], da1 = ad4[ct * 2 + 1];

    #pragma unroll
    for (int i = 0; i < 8; i++) {
        int row = row0 + r0 + i;
        float o[8];
        #pragma unroll
        for (int j = 0; j < 4; j++) {
            unsigned int lo, hi;
            asm("mov.b64 {%0, %1}, %2;" : "=r"(lo), "=r"(hi) : "l"(acc[i][j]));
            o[2 * j]     = __uint_as_float(lo);
            o[2 * j + 1] = __uint_as_float(hi);
        }
        float ps = o[0]*sa0.x + o[1]*sa0.y + o[2]*sa0.z + o[3]*sa0.w
                 + o[4]*sa1.x + o[5]*sa1.y + o[6]*sa1.z + o[7]*sa1.w;
        float pd = o[0]*da0.x + o[1]*da0.y + o[2]*da0.z + o[3]*da0.w
                 + o[4]*da1.x + o[5]*da1.y + o[6]*da1.z + o[7]*da1.w;
        #pragma unroll
        for (int m = 1; m < 8; m <<= 1) {
            ps += __shfl_xor_sync(0xffffffffu, ps, m);
            pd += __shfl_xor_sync(0xffffffffu, pd, m);
        }
        if (row < Nn) {
            __half2 p0 = __floats2half2_rn(o[0], o[1]);
            __half2 p1 = __floats2half2_rn(o[2], o[3]);
            __half2 p2 = __floats2half2_rn(o[4], o[5]);
            __half2 p3 = __floats2half2_rn(o[6], o[7]);
            uint4 pk;
            pk.x = *(unsigned int*)&p0; pk.y = *(unsigned int*)&p1;
            pk.z = *(unsigned int*)&p2; pk.w = *(unsigned int*)&p3;
            *(uint4*)(h + (size_t)row * 64 + ct * 8) = pk;
            if (ct == 0) { as_[row] = ps; ad_[row] = pd; }
        }
    }
}

// ---------------------------------------------------------------------------
// GEMM2: h2 = h1r @ W2 (K=64, C=40), fp16 output, alpha dots fused.
// ---------------------------------------------------------------------------
__global__ void gemm2_kernel(const float* __restrict__ x,
                             const float* __restrict__ W,
                             const float* __restrict__ asv,
                             const float* __restrict__ adv,
                             __half* __restrict__ h,
                             float* __restrict__ as_, float* __restrict__ ad_,
                             int Nn) {
    __shared__ float Xs[32][64];
    __shared__ float Ws[64][40];
    int tid = threadIdx.x;
    int row0 = blockIdx.x * 32;

    #pragma unroll
    for (int i = tid; i < 64 * 40; i += 128) Ws[i / 40][i % 40] = W[i];

    const float4* x4 = (const float4*)x;
    float4* Xs4 = (float4*)Xs;
    #pragma unroll
    for (int i = tid; i < 32 * 16; i += 128) {
        long long gi = (long long)row0 * 16 + i;
        Xs4[i] = (gi < (long long)Nn * 16) ? x4[gi] : make_float4(0.f, 0.f, 0.f, 0.f);
    }
    __syncthreads();

    int r0 = (tid >> 3) * 2;
    int c0 = (tid & 7) * 5;
    float acc[2][5] = {};
    #pragma unroll 4
    for (int k = 0; k < 64; k++) {
        float xv0 = Xs[r0][k];
        float xv1 = Xs[r0 + 1][k];
        #pragma unroll
        for (int j = 0; j < 5; j++) {
            float wv = Ws[k][c0 + j];
            acc[0][j] += xv0 * wv;
            acc[1][j] += xv1 * wv;
        }
    }

    float sa[5], da[5];
    #pragma unroll
    for (int j = 0; j < 5; j++) { sa[j] = asv[c0 + j]; da[j] = adv[c0 + j]; }

    #pragma unroll
    for (int i = 0; i < 2; i++) {
        int row = row0 + r0 + i;
        float ps = 0.f, pd = 0.f;
        #pragma unroll
        for (int j = 0; j < 5; j++) {
            ps += acc[i][j] * sa[j];
            pd += acc[i][j] * da[j];
        }
        #pragma unroll
        for (int m = 1; m < 8; m <<= 1) {
            ps += __shfl_xor_sync(0xffffffffu, ps, m);
            pd += __shfl_xor_sync(0xffffffffu, pd, m);
        }
        if (row < Nn) {
            __half* dstp = h + (size_t)row * 40 + c0;
            #pragma unroll
            for (int j = 0; j < 5; j++) dstp[j] = __float2half_rn(acc[i][j]);
            if ((tid & 7) == 0) { as_[row] = ps; ad_[row] = pd; }
        }
    }
}

// ---------------------------------------------------------------------------
// Fused GAT aggregation, one warp per destination (CSR), fp16 feature rows.
// 32 warps/block. Pass 1: lane-parallel exp, smem coef+idx cache (deg<=96).
// Pass 2: 16 edges / warp-iteration (4 per 8-lane subwarp).
// Epilogue: FINAL=false -> relu(acc+bias); FINAL=true -> fused log_softmax.
// ---------------------------------------------------------------------------
template <int F, bool FINAL>
__global__ void gat_agg_kernel(const int* __restrict__ srcs,
                               const int* __restrict__ off,
                               const float* __restrict__ as_,
                               const float* __restrict__ ad_,
                               const __half* __restrict__ h,
                               const float* __restrict__ bias,
                               float* __restrict__ outp, int Nn) {
    constexpr int LROW = F / 8;
    __shared__ float exco[32][96];
    __shared__ int   sso[32][96];
    int w = threadIdx.x >> 5, lane = threadIdx.x & 31;
    int d = blockIdx.x * 32 + w;
    if (d >= Nn) return;
    int beg = off[d], end = off[d + 1];
    int deg = end - beg;
    float advv = ad_[d];
    float* exc = exco[w];
    int*   ssc = sso[w];
    bool fits = (deg <= 96);

    // Pass 1
    float sum = 0.f;
    for (int i = lane; i < deg; i += 32) {
        int s = srcs[beg + i];
        float e = as_[s] + advv;
        e = (e > 0.f) ? e : 0.2f * e;
        float xv = __expf(e);
        if (fits) { exc[i] = xv; ssc[i] = s; }
        sum += xv;
    }
    #pragma unroll
    for (int m = 16; m; m >>= 1) sum += __shfl_xor_sync(0xffffffffu, sum, m);
    float rden = 1.0f / sum;
    __syncwarp();

    int g = lane >> 3, l8 = lane & 7;
    bool act = (l8 < LROW);
    float a[8] = {0.f, 0.f, 0.f, 0.f, 0.f, 0.f, 0.f, 0.f};
    const float4* h4 = (const float4*)h;

    if (fits) {
        for (int it = 0; it < deg; it += 16) {
            int e[4], idx[4], s[4];
            float c[4];
            #pragma unroll
            for (int q = 0; q < 4; q++) {
                e[q] = it + q * 4 + g;
                idx[q] = min(e[q], deg - 1);
                s[q] = ssc[idx[q]];
            }
            #pragma unroll
            for (int q = 0; q < 4; q++) {
                c[q] = exc[idx[q]] * rden;
                if (e[q] >= deg) c[q] = 0.f;
            }
            float4 v[4];
            #pragma unroll
            for (int q = 0; q < 4; q++)
                if (act) v[q] = __ldg(&h4[(size_t)s[q] * LROW + l8]);
            #pragma unroll
            for (int q = 0; q < 4; q++) {
                if (act) {
                    const __half2* hp = (const __half2*)&v[q];
                    float2 f0 = __half22float2(hp[0]);
                    float2 f1 = __half22float2(hp[1]);
                    float2 f2 = __half22float2(hp[2]);
                    float2 f3 = __half22float2(hp[3]);
                    a[0] = fmaf(f0.x, c[q], a[0]); a[1] = fmaf(f0.y, c[q], a[1]);
                    a[2] = fmaf(f1.x, c[q], a[2]); a[3] = fmaf(f1.y, c[q], a[3]);
                    a[4] = fmaf(f2.x, c[q], a[4]); a[5] = fmaf(f2.y, c[q], a[5]);
                    a[6] = fmaf(f3.x, c[q], a[6]); a[7] = fmaf(f3.y, c[q], a[7]);
                }
            }
        }
    } else {
        for (int it = 0; it < deg; it += 4) {
            int e = it + g;
            if (e < deg) {
                int s = srcs[beg + e];
                float ev = as_[s] + advv;
                ev = (ev > 0.f) ? ev : 0.2f * ev;
                float coef = __expf(ev) * rden;
                if (act) {
                    float4 v = __ldg(&h4[(size_t)s * LROW + l8]);
                    const __half2* hp = (const __half2*)&v;
                    float2 f0 = __half22float2(hp[0]);
                    float2 f1 = __half22float2(hp[1]);
                    float2 f2 = __half22float2(hp[2]);
                    float2 f3 = __half22float2(hp[3]);
                    a[0] = fmaf(f0.x, coef, a[0]); a[1] = fmaf(f0.y, coef, a[1]);
                    a[2] = fmaf(f1.x, coef, a[2]); a[3] = fmaf(f1.y, coef, a[3]);
                    a[4] = fmaf(f2.x, coef, a[4]); a[5] = fmaf(f2.y, coef, a[5]);
                    a[6] = fmaf(f3.x, coef, a[6]); a[7] = fmaf(f3.y, coef, a[7]);
                }
            }
        }
    }

    #pragma unroll
    for (int m = 8; m < 32; m <<= 1)
        #pragma unroll
        for (int j = 0; j < 8; j++)
            a[j] += __shfl_xor_sync(0xffffffffu, a[j], m);

    if (!FINAL) {
        if (lane < LROW) {
            float o[8];
            #pragma unroll
            for (int j = 0; j < 8; j++)
                o[j] = fmaxf(a[j] + bias[l8 * 8 + j], 0.f);
            float* dstp = outp + (size_t)d * F + l8 * 8;
            *(float4*)dstp       = make_float4(o[0], o[1], o[2], o[3]);
            *(float4*)(dstp + 4) = make_float4(o[4], o[5], o[6], o[7]);
        }
    } else {
        float v[8];
        float mx = __int_as_float(0xff800000);
        if (act) {
            #pragma unroll
            for (int j = 0; j < 8; j++) {
                v[j] = a[j] + bias[l8 * 8 + j];
                mx = fmaxf(mx, v[j]);
            }
        }
        #pragma unroll
        for (int m = 1; m < 8; m <<= 1) mx = fmaxf(mx, __shfl_xor_sync(0xffffffffu, mx, m));
        float se = 0.f;
        if (act) {
            #pragma unroll
            for (int j = 0; j < 8; j++) se += __expf(v[j] - mx);
        }
        #pragma unroll
        for (int m = 1; m < 8; m <<= 1) se += __shfl_xor_sync(0xffffffffu, se, m);
        float ls = mx + __logf(se);
        if (lane < LROW) {
            float* dstp = outp + (size_t)d * F + l8 * 8;
            *(float4*)dstp       = make_float4(v[0] - ls, v[1] - ls, v[2] - ls, v[3] - ls);
            *(float4*)(dstp + 4) = make_float4(v[4] - ls, v[5] - ls, v[6] - ls, v[7] - ls);
        }
    }
}

// ---------------------------------------------------------------------------
// Launch.  Kernel order: csr_a(1) csr_b(2) gemm1(3) agg1(4) gemm2(5) agg2(6)
// -> the profiler's capture slot lands on agg1.
// ---------------------------------------------------------------------------
extern "C" void kernel_launch(void* const* d_in, const int* in_sizes, int n_in,
                              void* d_out, int out_size) {
    const float* x       = (const float*)d_in[0];
    const unsigned int* ei_raw = (const unsigned int*)d_in[1];
    const float* W1      = (const float*)d_in[2];
    const float* a_src1  = (const float*)d_in[3];
    const float* a_dst1  = (const float*)d_in[4];
    const float* b1      = (const float*)d_in[5];
    const float* W2      = (const float*)d_in[6];
    const float* a_src2  = (const float*)d_in[7];
    const float* a_dst2  = (const float*)d_in[8];
    const float* b2      = (const float*)d_in[9];
    float* out           = (float*)d_out;

    int Nn = in_sizes[0] / 128;
    long long E = in_sizes[1] / 2;
    long long T = E + Nn;

    float *p_h1r, *p_as, *p_ad;
    __half *p_h1h, *p_h2h;
    int *p_cnt, *p_off, *p_srcs, *p_rank, *p_part, *p_bars, *p_is64;
    cudaGetSymbolAddress((void**)&p_h1h, g_h1h);
    cudaGetSymbolAddress((void**)&p_h1r, g_h1r);
    cudaGetSymbolAddress((void**)&p_h2h, g_h2h);
    cudaGetSymbolAddress((void**)&p_as, g_as);
    cudaGetSymbolAddress((void**)&p_ad, g_ad);
    cudaGetSymbolAddress((void**)&p_cnt, g_cnt);
    cudaGetSymbolAddress((void**)&p_off, g_off);
    cudaGetSymbolAddress((void**)&p_srcs, g_srcs);
    cudaGetSymbolAddress((void**)&p_rank, g_rank);
    cudaGetSymbolAddress((void**)&p_part, g_partials);
    cudaGetSymbolAddress((void**)&p_bars, g_bars);
    cudaGetSymbolAddress((void**)&p_is64, g_is64);

    static cudaStream_t s2 = nullptr;
    static cudaEvent_t evF = nullptr, evC = nullptr;
    if (!s2) {
        cudaStreamCreateWithFlags(&s2, cudaStreamNonBlocking);
        cudaEventCreateWithFlags(&evF, cudaEventDisableTiming);
        cudaEventCreateWithFlags(&evC, cudaEventDisableTiming);
    }

    int nb = (Nn + 1023) / 1024;   // 98

    // ---- Fork: CSR build on s2 (2 cooperative kernels), gemm1 on main ----
    cudaEventRecord(evF, 0);
    cudaStreamWaitEvent(s2, evF, 0);

    cudaMemsetAsync(p_bars, 0, 3 * sizeof(int), s2);
    csr_a_kernel<<<148, 1024, 0, s2>>>(ei_raw, p_cnt, p_rank, p_is64, p_bars, Nn, E);
    csr_b_kernel<<<nb, 1024, 0, s2>>>(ei_raw, p_cnt, p_rank, p_off, p_srcs,
                                      p_part, p_bars, p_is64, Nn, E, T);
    cudaEventRecord(evC, s2);

    gemm1_kernel<<<(Nn + 127) / 128, 128>>>(x, W1, a_src1, a_dst1, p_h1h, p_as, p_ad, Nn);

    // ---- Join ----
    cudaStreamWaitEvent(0, evC, 0);
    gat_agg_kernel<64, false><<<(Nn + 31) / 32, 1024>>>(p_srcs, p_off, p_as, p_ad, p_h1h, b1, p_h1r, Nn);
    gemm2_kernel<<<(Nn + 31) / 32, 128>>>(p_h1r, W2, a_src2, a_dst2, p_h2h, p_as, p_ad, Nn);
    gat_agg_kernel<40, true><<<(Nn + 31) / 32, 1024>>>(p_srcs, p_off, p_as, p_ad, p_h2h, b2, out, Nn);
}

// round 13
// speedup vs baseline: 1.2250x; 1.2250x over previous
#include <cuda_runtime.h>
#include <cuda_fp16.h>
#include <math.h>

// ---------------------------------------------------------------------------
// N=100000, F_in=128, F_hid=64, F_out=40, E=1600000 (+N self loops).
// h1 / h2 stored fp16; fp32 accumulation everywhere.
// ---------------------------------------------------------------------------
#define MAXN 100000
#define MAXE 1700096

__device__ __half g_h1h[(size_t)MAXN * 64];
__device__ float  g_h1r[(size_t)MAXN * 64];
__device__ __half g_h2h[(size_t)MAXN * 40];
__device__ float  g_as[MAXN];
__device__ float  g_ad[MAXN];
__device__ int    g_cnt[MAXN];
__device__ int    g_off[MAXN + 1];
__device__ int    g_srcs[MAXE];
__device__ int    g_rank[MAXE];
__device__ int    g_partials[128];
__device__ int    g_barrier;
__device__ int    g_is64;

// ---------------------------------------------------------------------------
// Init + dtype detect
// ---------------------------------------------------------------------------
__global__ void init_detect_kernel(const unsigned int* __restrict__ w,
                                   int* __restrict__ cnt, int* flag,
                                   int* barrier, int n) {
    int i = blockIdx.x * blockDim.x + threadIdx.x;
    int stride = gridDim.x * blockDim.x;
    for (int j = i; j < n; j += stride) cnt[j] = 0;
    if (blockIdx.x == 0) {
        __shared__ int any;
        if (threadIdx.x == 0) { any = 0; *barrier = 0; }
        __syncthreads();
        for (int k = threadIdx.x; k < 1024; k += blockDim.x)
            if (w[2 * k + 1] != 0u) atomicOr(&any, 1);
        __syncthreads();
        if (threadIdx.x == 0) *flag = any ? 0 : 1;  // 1 => int64
    }
}

// ---------------------------------------------------------------------------
// Hist: count destinations AND record each edge's rank within its dst.
// ---------------------------------------------------------------------------
__global__ void hist_kernel(const unsigned int* __restrict__ w,
                            int* __restrict__ cnt, int* __restrict__ rank,
                            long long E, const int* __restrict__ flag) {
    long long i = (long long)blockIdx.x * blockDim.x + threadIdx.x;
    if (i >= E) return;
    int is64 = *flag;
    int d = is64 ? (int)((const uint2*)w)[E + i].x : (int)w[E + i];
    rank[i] = atomicAdd(&cnt[d], 1);
}

// ---------------------------------------------------------------------------
// One-kernel exclusive scan of (cnt[i]+1) -> off.
// ---------------------------------------------------------------------------
__global__ void scan_kernel(const int* __restrict__ cnt,
                            int* __restrict__ off,
                            int* __restrict__ partials, int* __restrict__ barrier,
                            int n, int total) {
    __shared__ int sm[1024];
    __shared__ int pf[128];
    int tid = threadIdx.x, b = blockIdx.x;
    int i = b * 1024 + tid;
    int v = (i < n) ? cnt[i] + 1 : 0;   // +1 = self loop
    sm[tid] = v;
    __syncthreads();
    #pragma unroll
    for (int o = 1; o < 1024; o <<= 1) {
        int t = (tid >= o) ? sm[tid - o] : 0;
        __syncthreads();
        sm[tid] += t;
        __syncthreads();
    }
    int incl = sm[tid];

    if (tid == 0) {
        partials[b] = sm[1023];
        __threadfence();
        atomicAdd(barrier, 1);
        while (atomicAdd(barrier, 0) < gridDim.x) {}
    }
    __syncthreads();

    pf[tid & 127] = 0;
    __syncthreads();
    if (tid < 128) pf[tid] = (tid < b) ? partials[tid] : 0;
    __syncthreads();
    #pragma unroll
    for (int o = 64; o; o >>= 1) {
        if (tid < o) pf[tid] += pf[tid + o];
        __syncthreads();
    }
    int prefix = pf[0];

    if (i < n) off[i] = prefix + incl - v;
    if (i == 0) off[n] = total;
}

// ---------------------------------------------------------------------------
// Fill: atomic-free scatter using precomputed ranks.
// ---------------------------------------------------------------------------
__global__ void fill_kernel(const unsigned int* __restrict__ w,
                            const int* __restrict__ off,
                            const int* __restrict__ cnt,
                            const int* __restrict__ rank,
                            int* __restrict__ srcs,
                            long long E, long long T,
                            const int* __restrict__ flag) {
    long long t = (long long)blockIdx.x * blockDim.x + threadIdx.x;
    if (t >= T) return;
    int is64 = *flag;
    if (t < E) {
        int s, d;
        if (is64) {
            const uint2* w2 = (const uint2*)w;
            s = (int)w2[t].x;
            d = (int)w2[E + t].x;
        } else {
            s = (int)w[t];
            d = (int)w[E + t];
        }
        srcs[off[d] + rank[t]] = s;
    } else {
        int d = (int)(t - E);
        srcs[off[d] + cnt[d]] = d;
    }
}

// ---------------------------------------------------------------------------
// GEMM1: h = x @ W (K=128, C=64), fp32 accumulation, fp16 output rows.
// ---------------------------------------------------------------------------
__global__ void gemm1_kernel(const float* __restrict__ x,
                             const float* __restrict__ W,
                             const float* __restrict__ asv,
                             const float* __restrict__ adv,
                             __half* __restrict__ h,
                             float* __restrict__ as_, float* __restrict__ ad_,
                             int Nn) {
    __shared__ float Xs[128 * 32];
    __shared__ float Ws[32 * 64];
    int tid = threadIdx.x;
    int row0 = blockIdx.x * 128;
    int rt = tid >> 3;
    int ct = tid & 7;
    int r0 = rt * 8;
    int kx = (rt & 3) << 3;

    unsigned long long acc[8][4];
    #pragma unroll
    for (int i = 0; i < 8; i++)
        #pragma unroll
        for (int j = 0; j < 4; j++) acc[i][j] = 0ull;

    const float4* x4 = (const float4*)x;

    for (int kc = 0; kc < 4; kc++) {
        const float4* W4 = (const float4*)(W + kc * 32 * 64);
        #pragma unroll
        for (int i = tid; i < 512; i += 128) ((float4*)Ws)[i] = W4[i];
        #pragma unroll
        for (int i = tid; i < 1024; i += 128) {
            int row = i >> 3;
            int c4  = i & 7;
            int gr = row0 + row;
            float4 v = (gr < Nn) ? x4[(size_t)gr * 32 + kc * 8 + c4]
                                 : make_float4(0.f, 0.f, 0.f, 0.f);
            int col = (c4 * 4) ^ (((row >> 3) & 3) << 3);
            *(float4*)&Xs[row * 32 + col] = v;
        }
        __syncthreads();

        #pragma unroll
        for (int k = 0; k < 32; k++) {
            longlong2 w0 = *(const longlong2*)&Ws[k * 64 + ct * 8];
            longlong2 w1 = *(const longlong2*)&Ws[k * 64 + ct * 8 + 4];
            #pragma unroll
            for (int i = 0; i < 8; i++) {
                float xv = Xs[(r0 + i) * 32 + (k ^ kx)];
                unsigned long long xx;
                asm("mov.b64 %0, {%1, %1};" : "=l"(xx) : "r"(__float_as_uint(xv)));
                asm("fma.rn.f32x2 %0, %1, %2, %0;" : "+l"(acc[i][0]) : "l"(xx), "l"((unsigned long long)w0.x));
                asm("fma.rn.f32x2 %0, %1, %2, %0;" : "+l"(acc[i][1]) : "l"(xx), "l"((unsigned long long)w0.y));
                asm("fma.rn.f32x2 %0, %1, %2, %0;" : "+l"(acc[i][2]) : "l"(xx), "l"((unsigned long long)w1.x));
                asm("fma.rn.f32x2 %0, %1, %2, %0;" : "+l"(acc[i][3]) : "l"(xx), "l"((unsigned long long)w1.y));
            }
        }
        __syncthreads();
    }

    const float4* as4 = (const float4*)asv;
    const float4* ad4 = (const float4*)adv;
    float4 sa0 = as4[ct * 2], sa1 = as4[ct * 2 + 1];
    float4 da0 = ad4[ct * 2], da1 = ad4[ct * 2 + 1];

    #pragma unroll
    for (int i = 0; i < 8; i++) {
        int row = row0 + r0 + i;
        float o[8];
        #pragma unroll
        for (int j = 0; j < 4; j++) {
            unsigned int lo, hi;
            asm("mov.b64 {%0, %1}, %2;" : "=r"(lo), "=r"(hi) : "l"(acc[i][j]));
            o[2 * j]     = __uint_as_float(lo);
            o[2 * j + 1] = __uint_as_float(hi);
        }
        float ps = o[0]*sa0.x + o[1]*sa0.y + o[2]*sa0.z + o[3]*sa0.w
                 + o[4]*sa1.x + o[5]*sa1.y + o[6]*sa1.z + o[7]*sa1.w;
        float pd = o[0]*da0.x + o[1]*da0.y + o[2]*da0.z + o[3]*da0.w
                 + o[4]*da1.x + o[5]*da1.y + o[6]*da1.z + o[7]*da1.w;
        #pragma unroll
        for (int m = 1; m < 8; m <<= 1) {
            ps += __shfl_xor_sync(0xffffffffu, ps, m);
            pd += __shfl_xor_sync(0xffffffffu, pd, m);
        }
        if (row < Nn) {
            __half2 p0 = __floats2half2_rn(o[0], o[1]);
            __half2 p1 = __floats2half2_rn(o[2], o[3]);
            __half2 p2 = __floats2half2_rn(o[4], o[5]);
            __half2 p3 = __floats2half2_rn(o[6], o[7]);
            uint4 pk;
            pk.x = *(unsigned int*)&p0; pk.y = *(unsigned int*)&p1;
            pk.z = *(unsigned int*)&p2; pk.w = *(unsigned int*)&p3;
            *(uint4*)(h + (size_t)row * 64 + ct * 8) = pk;
            if (ct == 0) { as_[row] = ps; ad_[row] = pd; }
        }
    }
}

// ---------------------------------------------------------------------------
// GEMM2: h2 = h1r @ W2 (K=64, C=40), fp16 output, alpha dots fused.
// ---------------------------------------------------------------------------
__global__ void gemm2_kernel(const float* __restrict__ x,
                             const float* __restrict__ W,
                             const float* __restrict__ asv,
                             const float* __restrict__ adv,
                             __half* __restrict__ h,
                             float* __restrict__ as_, float* __restrict__ ad_,
                             int Nn) {
    __shared__ float Xs[32][64];
    __shared__ float Ws[64][40];
    int tid = threadIdx.x;
    int row0 = blockIdx.x * 32;

    #pragma unroll
    for (int i = tid; i < 64 * 40; i += 128) Ws[i / 40][i % 40] = W[i];

    const float4* x4 = (const float4*)x;
    float4* Xs4 = (float4*)Xs;
    #pragma unroll
    for (int i = tid; i < 32 * 16; i += 128) {
        long long gi = (long long)row0 * 16 + i;
        Xs4[i] = (gi < (long long)Nn * 16) ? x4[gi] : make_float4(0.f, 0.f, 0.f, 0.f);
    }
    __syncthreads();

    int r0 = (tid >> 3) * 2;
    int c0 = (tid & 7) * 5;
    float acc[2][5] = {};
    #pragma unroll 4
    for (int k = 0; k < 64; k++) {
        float xv0 = Xs[r0][k];
        float xv1 = Xs[r0 + 1][k];
        #pragma unroll
        for (int j = 0; j < 5; j++) {
            float wv = Ws[k][c0 + j];
            acc[0][j] += xv0 * wv;
            acc[1][j] += xv1 * wv;
        }
    }

    float sa[5], da[5];
    #pragma unroll
    for (int j = 0; j < 5; j++) { sa[j] = asv[c0 + j]; da[j] = adv[c0 + j]; }

    #pragma unroll
    for (int i = 0; i < 2; i++) {
        int row = row0 + r0 + i;
        float ps = 0.f, pd = 0.f;
        #pragma unroll
        for (int j = 0; j < 5; j++) {
            ps += acc[i][j] * sa[j];
            pd += acc[i][j] * da[j];
        }
        #pragma unroll
        for (int m = 1; m < 8; m <<= 1) {
            ps += __shfl_xor_sync(0xffffffffu, ps, m);
            pd += __shfl_xor_sync(0xffffffffu, pd, m);
        }
        if (row < Nn) {
            __half* dstp = h + (size_t)row * 40 + c0;
            #pragma unroll
            for (int j = 0; j < 5; j++) dstp[j] = __float2half_rn(acc[i][j]);
            if ((tid & 7) == 0) { as_[row] = ps; ad_[row] = pd; }
        }
    }
}

// ---------------------------------------------------------------------------
// Fused GAT aggregation, one warp per destination (CSR), fp16 feature rows.
// ISSUE-OPTIMIZED: rden hoisted out of the edge loop (applied once at the
// end), clamp-free main loop over full 16-edge chunks + one clamped tail,
// 32-bit gather address arithmetic.
// ---------------------------------------------------------------------------
template <int F, bool FINAL>
__global__ void gat_agg_kernel(const int* __restrict__ srcs,
                               const int* __restrict__ off,
                               const float* __restrict__ as_,
                               const float* __restrict__ ad_,
                               const __half* __restrict__ h,
                               const float* __restrict__ bias,
                               float* __restrict__ outp, int Nn) {
    constexpr int LROW = F / 8;
    __shared__ float exco[8][96];
    __shared__ int   sso[8][96];
    int w = threadIdx.x >> 5, lane = threadIdx.x & 31;
    int d = blockIdx.x * 8 + w;
    if (d >= Nn) return;
    int beg = off[d], end = off[d + 1];
    int deg = end - beg;
    float advv = ad_[d];
    float* exc = exco[w];
    int*   ssc = sso[w];
    bool fits = (deg <= 96);

    // Pass 1: exp numerators + sum
    float sum = 0.f;
    for (int i = lane; i < deg; i += 32) {
        int s = srcs[beg + i];
        float e = as_[s] + advv;
        e = (e > 0.f) ? e : 0.2f * e;
        float xv = __expf(e);
        if (fits) { exc[i] = xv; ssc[i] = s; }
        sum += xv;
    }
    #pragma unroll
    for (int m = 16; m; m >>= 1) sum += __shfl_xor_sync(0xffffffffu, sum, m);
    float rden = 1.0f / sum;
    __syncwarp();

    int g = lane >> 3, l8 = lane & 7;
    bool act = (l8 < LROW);
    float a[8] = {0.f, 0.f, 0.f, 0.f, 0.f, 0.f, 0.f, 0.f};
    const float4* h4 = (const float4*)h;

    if (fits) {
        int full = deg & ~15;
        int it = 0;
        // clamp-free main loop over full 16-edge chunks
        for (; it < full; it += 16) {
            int s0 = ssc[it + g],      s1 = ssc[it + 4 + g];
            int s2 = ssc[it + 8 + g],  s3 = ssc[it + 12 + g];
            float c0 = exc[it + g],     c1 = exc[it + 4 + g];
            float c2 = exc[it + 8 + g], c3 = exc[it + 12 + g];
            float4 v0, v1, v2, v3;
            if (act) {
                v0 = __ldg(&h4[s0 * LROW + l8]);
                v1 = __ldg(&h4[s1 * LROW + l8]);
                v2 = __ldg(&h4[s2 * LROW + l8]);
                v3 = __ldg(&h4[s3 * LROW + l8]);
            }
            if (act) {
                #define ACC8(vv, cc) { \
                    const __half2* hp = (const __half2*)&(vv); \
                    float2 f0 = __half22float2(hp[0]); \
                    float2 f1 = __half22float2(hp[1]); \
                    float2 f2 = __half22float2(hp[2]); \
                    float2 f3 = __half22float2(hp[3]); \
                    a[0] = fmaf(f0.x, (cc), a[0]); a[1] = fmaf(f0.y, (cc), a[1]); \
                    a[2] = fmaf(f1.x, (cc), a[2]); a[3] = fmaf(f1.y, (cc), a[3]); \
                    a[4] = fmaf(f2.x, (cc), a[4]); a[5] = fmaf(f2.y, (cc), a[5]); \
                    a[6] = fmaf(f3.x, (cc), a[6]); a[7] = fmaf(f3.y, (cc), a[7]); }
                ACC8(v0, c0) ACC8(v1, c1) ACC8(v2, c2) ACC8(v3, c3)
            }
        }
        // single clamped tail chunk
        if (it < deg) {
            #pragma unroll
            for (int q = 0; q < 4; q++) {
                int e = it + q * 4 + g;
                int idx = min(e, deg - 1);
                int s = ssc[idx];
                float c = (e < deg) ? exc[idx] : 0.f;
                if (act) {
                    float4 v = __ldg(&h4[s * LROW + l8]);
                    ACC8(v, c)
                }
            }
        }
        #undef ACC8
    } else {
        for (int it = 0; it < deg; it += 4) {
            int e = it + g;
            if (e < deg) {
                int s = srcs[beg + e];
                float ev = as_[s] + advv;
                ev = (ev > 0.f) ? ev : 0.2f * ev;
                float c = __expf(ev);
                if (act) {
                    float4 v = __ldg(&h4[s * LROW + l8]);
                    const __half2* hp = (const __half2*)&v;
                    float2 f0 = __half22float2(hp[0]);
                    float2 f1 = __half22float2(hp[1]);
                    float2 f2 = __half22float2(hp[2]);
                    float2 f3 = __half22float2(hp[3]);
                    a[0] = fmaf(f0.x, c, a[0]); a[1] = fmaf(f0.y, c, a[1]);
                    a[2] = fmaf(f1.x, c, a[2]); a[3] = fmaf(f1.y, c, a[3]);
                    a[4] = fmaf(f2.x, c, a[4]); a[5] = fmaf(f2.y, c, a[5]);
                    a[6] = fmaf(f3.x, c, a[6]); a[7] = fmaf(f3.y, c, a[7]);
                }
            }
        }
    }

    // Combine the 4 subwarps, then apply 1/den once (linearity).
    #pragma unroll
    for (int m = 8; m < 32; m <<= 1)
        #pragma unroll
        for (int j = 0; j < 8; j++)
            a[j] += __shfl_xor_sync(0xffffffffu, a[j], m);
    #pragma unroll
    for (int j = 0; j < 8; j++) a[j] *= rden;

    if (!FINAL) {
        if (lane < LROW) {
            float o[8];
            #pragma unroll
            for (int j = 0; j < 8; j++)
                o[j] = fmaxf(a[j] + bias[l8 * 8 + j], 0.f);
            float* dstp = outp + (size_t)d * F + l8 * 8;
            *(float4*)dstp       = make_float4(o[0], o[1], o[2], o[3]);
            *(float4*)(dstp + 4) = make_float4(o[4], o[5], o[6], o[7]);
        }
    } else {
        float v[8];
        float mx = __int_as_float(0xff800000);
        if (act) {
            #pragma unroll
            for (int j = 0; j < 8; j++) {
                v[j] = a[j] + bias[l8 * 8 + j];
                mx = fmaxf(mx, v[j]);
            }
        }
        #pragma unroll
        for (int m = 1; m < 8; m <<= 1) mx = fmaxf(mx, __shfl_xor_sync(0xffffffffu, mx, m));
        float se = 0.f;
        if (act) {
            #pragma unroll
            for (int j = 0; j < 8; j++) se += __expf(v[j] - mx);
        }
        #pragma unroll
        for (int m = 1; m < 8; m <<= 1) se += __shfl_xor_sync(0xffffffffu, se, m);
        float ls = mx + __logf(se);
        if (lane < LROW) {
            float* dstp = outp + (size_t)d * F + l8 * 8;
            *(float4*)dstp       = make_float4(v[0] - ls, v[1] - ls, v[2] - ls, v[3] - ls);
            *(float4*)(dstp + 4) = make_float4(v[4] - ls, v[5] - ls, v[6] - ls, v[7] - ls);
        }
    }
}

// ---------------------------------------------------------------------------
// Launch: CSR build on side stream, overlapped with gemm1.
// ---------------------------------------------------------------------------
extern "C" void kernel_launch(void* const* d_in, const int* in_sizes, int n_in,
                              void* d_out, int out_size) {
    const float* x       = (const float*)d_in[0];
    const unsigned int* ei_raw = (const unsigned int*)d_in[1];
    const float* W1      = (const float*)d_in[2];
    const float* a_src1  = (const float*)d_in[3];
    const float* a_dst1  = (const float*)d_in[4];
    const float* b1      = (const float*)d_in[5];
    const float* W2      = (const float*)d_in[6];
    const float* a_src2  = (const float*)d_in[7];
    const float* a_dst2  = (const float*)d_in[8];
    const float* b2      = (const float*)d_in[9];
    float* out           = (float*)d_out;

    int Nn = in_sizes[0] / 128;
    long long E = in_sizes[1] / 2;
    long long T = E + Nn;

    float *p_h1r, *p_as, *p_ad;
    __half *p_h1h, *p_h2h;
    int *p_cnt, *p_off, *p_srcs, *p_rank, *p_part, *p_bar, *p_is64;
    cudaGetSymbolAddress((void**)&p_h1h, g_h1h);
    cudaGetSymbolAddress((void**)&p_h1r, g_h1r);
    cudaGetSymbolAddress((void**)&p_h2h, g_h2h);
    cudaGetSymbolAddress((void**)&p_as, g_as);
    cudaGetSymbolAddress((void**)&p_ad, g_ad);
    cudaGetSymbolAddress((void**)&p_cnt, g_cnt);
    cudaGetSymbolAddress((void**)&p_off, g_off);
    cudaGetSymbolAddress((void**)&p_srcs, g_srcs);
    cudaGetSymbolAddress((void**)&p_rank, g_rank);
    cudaGetSymbolAddress((void**)&p_part, g_partials);
    cudaGetSymbolAddress((void**)&p_bar, g_barrier);
    cudaGetSymbolAddress((void**)&p_is64, g_is64);

    static cudaStream_t s2 = nullptr;
    static cudaEvent_t evF = nullptr, evC = nullptr;
    if (!s2) {
        cudaStreamCreateWithFlags(&s2, cudaStreamNonBlocking);
        cudaEventCreateWithFlags(&evF, cudaEventDisableTiming);
        cudaEventCreateWithFlags(&evC, cudaEventDisableTiming);
    }

    const int TB = 256;
    int nb = (Nn + 1023) / 1024;   // 98

    // ---- Fork: CSR build on s2, gemm1 on main stream ----
    cudaEventRecord(evF, 0);
    cudaStreamWaitEvent(s2, evF, 0);

    init_detect_kernel<<<392, 256, 0, s2>>>(ei_raw, p_cnt, p_is64, p_bar, Nn);
    hist_kernel<<<(int)((E + TB - 1) / TB), TB, 0, s2>>>(ei_raw, p_cnt, p_rank, E, p_is64);
    scan_kernel<<<nb, 1024, 0, s2>>>(p_cnt, p_off, p_part, p_bar, Nn, (int)T);
    fill_kernel<<<(int)((T + TB - 1) / TB), TB, 0, s2>>>(ei_raw, p_off, p_cnt, p_rank, p_srcs, E, T, p_is64);
    cudaEventRecord(evC, s2);

    gemm1_kernel<<<(Nn + 127) / 128, 128>>>(x, W1, a_src1, a_dst1, p_h1h, p_as, p_ad, Nn);

    // ---- Join ----
    cudaStreamWaitEvent(0, evC, 0);
    gat_agg_kernel<64, false><<<(Nn + 7) / 8, 256>>>(p_srcs, p_off, p_as, p_ad, p_h1h, b1, p_h1r, Nn);
    gemm2_kernel<<<(Nn + 31) / 32, 128>>>(p_h1r, W2, a_src2, a_dst2, p_h2h, p_as, p_ad, Nn);
    gat_agg_kernel<40, true><<<(Nn + 7) / 8, 256>>>(p_srcs, p_off, p_as, p_ad, p_h2h, b2, out, Nn);
}

// round 14
// speedup vs baseline: 1.2758x; 1.0415x over previous
#include <cuda_runtime.h>
#include <cuda_fp16.h>
#include <math.h>

// ---------------------------------------------------------------------------
// N=100000, F_in=128, F_hid=64, F_out=40, E=1600000 (+N self loops).
// h1 / h2 stored fp16; agg accumulates 4-edge chunks in HFMA2, fp32 across
// chunks (issue-bound kernel: conversions were the dominant instruction).
// ---------------------------------------------------------------------------
#define MAXN 100000
#define MAXE 1700096

__device__ __half g_h1h[(size_t)MAXN * 64];
__device__ float  g_h1r[(size_t)MAXN * 64];
__device__ __half g_h2h[(size_t)MAXN * 40];
__device__ float  g_as[MAXN];
__device__ float  g_ad[MAXN];
__device__ int    g_cnt[MAXN];
__device__ int    g_off[MAXN + 1];
__device__ int    g_srcs[MAXE];
__device__ int    g_rank[MAXE];
__device__ int    g_partials[128];
__device__ int    g_barrier;
__device__ int    g_is64;

// ---------------------------------------------------------------------------
// Init + dtype detect
// ---------------------------------------------------------------------------
__global__ void init_detect_kernel(const unsigned int* __restrict__ w,
                                   int* __restrict__ cnt, int* flag,
                                   int* barrier, int n) {
    int i = blockIdx.x * blockDim.x + threadIdx.x;
    int stride = gridDim.x * blockDim.x;
    for (int j = i; j < n; j += stride) cnt[j] = 0;
    if (blockIdx.x == 0) {
        __shared__ int any;
        if (threadIdx.x == 0) { any = 0; *barrier = 0; }
        __syncthreads();
        for (int k = threadIdx.x; k < 1024; k += blockDim.x)
            if (w[2 * k + 1] != 0u) atomicOr(&any, 1);
        __syncthreads();
        if (threadIdx.x == 0) *flag = any ? 0 : 1;  // 1 => int64
    }
}

// ---------------------------------------------------------------------------
// Hist: count destinations AND record each edge's rank within its dst.
// ---------------------------------------------------------------------------
__global__ void hist_kernel(const unsigned int* __restrict__ w,
                            int* __restrict__ cnt, int* __restrict__ rank,
                            long long E, const int* __restrict__ flag) {
    long long i = (long long)blockIdx.x * blockDim.x + threadIdx.x;
    if (i >= E) return;
    int is64 = *flag;
    int d = is64 ? (int)((const uint2*)w)[E + i].x : (int)w[E + i];
    rank[i] = atomicAdd(&cnt[d], 1);
}

// ---------------------------------------------------------------------------
// One-kernel exclusive scan of (cnt[i]+1) -> off.
// ---------------------------------------------------------------------------
__global__ void scan_kernel(const int* __restrict__ cnt,
                            int* __restrict__ off,
                            int* __restrict__ partials, int* __restrict__ barrier,
                            int n, int total) {
    __shared__ int sm[1024];
    __shared__ int pf[128];
    int tid = threadIdx.x, b = blockIdx.x;
    int i = b * 1024 + tid;
    int v = (i < n) ? cnt[i] + 1 : 0;   // +1 = self loop
    sm[tid] = v;
    __syncthreads();
    #pragma unroll
    for (int o = 1; o < 1024; o <<= 1) {
        int t = (tid >= o) ? sm[tid - o] : 0;
        __syncthreads();
        sm[tid] += t;
        __syncthreads();
    }
    int incl = sm[tid];

    if (tid == 0) {
        partials[b] = sm[1023];
        __threadfence();
        atomicAdd(barrier, 1);
        while (atomicAdd(barrier, 0) < gridDim.x) {}
    }
    __syncthreads();

    pf[tid & 127] = 0;
    __syncthreads();
    if (tid < 128) pf[tid] = (tid < b) ? partials[tid] : 0;
    __syncthreads();
    #pragma unroll
    for (int o = 64; o; o >>= 1) {
        if (tid < o) pf[tid] += pf[tid + o];
        __syncthreads();
    }
    int prefix = pf[0];

    if (i < n) off[i] = prefix + incl - v;
    if (i == 0) off[n] = total;
}

// ---------------------------------------------------------------------------
// Fill: atomic-free scatter using precomputed ranks.
// ---------------------------------------------------------------------------
__global__ void fill_kernel(const unsigned int* __restrict__ w,
                            const int* __restrict__ off,
                            const int* __restrict__ cnt,
                            const int* __restrict__ rank,
                            int* __restrict__ srcs,
                            long long E, long long T,
                            const int* __restrict__ flag) {
    long long t = (long long)blockIdx.x * blockDim.x + threadIdx.x;
    if (t >= T) return;
    int is64 = *flag;
    if (t < E) {
        int s, d;
        if (is64) {
            const uint2* w2 = (const uint2*)w;
            s = (int)w2[t].x;
            d = (int)w2[E + t].x;
        } else {
            s = (int)w[t];
            d = (int)w[E + t];
        }
        srcs[off[d] + rank[t]] = s;
    } else {
        int d = (int)(t - E);
        srcs[off[d] + cnt[d]] = d;
    }
}

// ---------------------------------------------------------------------------
// GEMM1: h = x @ W (K=128, C=64), fp32 accumulation, fp16 output rows.
// Alpha dots fused into epilogue.
// ---------------------------------------------------------------------------
__global__ void gemm1_kernel(const float* __restrict__ x,
                             const float* __restrict__ W,
                             const float* __restrict__ asv,
                             const float* __restrict__ adv,
                             __half* __restrict__ h,
                             float* __restrict__ as_, float* __restrict__ ad_,
                             int Nn) {
    __shared__ float Xs[128 * 32];
    __shared__ float Ws[32 * 64];
    int tid = threadIdx.x;
    int row0 = blockIdx.x * 128;
    int rt = tid >> 3;
    int ct = tid & 7;
    int r0 = rt * 8;
    int kx = (rt & 3) << 3;

    unsigned long long acc[8][4];
    #pragma unroll
    for (int i = 0; i < 8; i++)
        #pragma unroll
        for (int j = 0; j < 4; j++) acc[i][j] = 0ull;

    const float4* x4 = (const float4*)x;

    for (int kc = 0; kc < 4; kc++) {
        const float4* W4 = (const float4*)(W + kc * 32 * 64);
        #pragma unroll
        for (int i = tid; i < 512; i += 128) ((float4*)Ws)[i] = W4[i];
        #pragma unroll
        for (int i = tid; i < 1024; i += 128) {
            int row = i >> 3;
            int c4  = i & 7;
            int gr = row0 + row;
            float4 v = (gr < Nn) ? x4[(size_t)gr * 32 + kc * 8 + c4]
                                 : make_float4(0.f, 0.f, 0.f, 0.f);
            int col = (c4 * 4) ^ (((row >> 3) & 3) << 3);
            *(float4*)&Xs[row * 32 + col] = v;
        }
        __syncthreads();

        #pragma unroll
        for (int k = 0; k < 32; k++) {
            longlong2 w0 = *(const longlong2*)&Ws[k * 64 + ct * 8];
            longlong2 w1 = *(const longlong2*)&Ws[k * 64 + ct * 8 + 4];
            #pragma unroll
            for (int i = 0; i < 8; i++) {
                float xv = Xs[(r0 + i) * 32 + (k ^ kx)];
                unsigned long long xx;
                asm("mov.b64 %0, {%1, %1};" : "=l"(xx) : "r"(__float_as_uint(xv)));
                asm("fma.rn.f32x2 %0, %1, %2, %0;" : "+l"(acc[i][0]) : "l"(xx), "l"((unsigned long long)w0.x));
                asm("fma.rn.f32x2 %0, %1, %2, %0;" : "+l"(acc[i][1]) : "l"(xx), "l"((unsigned long long)w0.y));
                asm("fma.rn.f32x2 %0, %1, %2, %0;" : "+l"(acc[i][2]) : "l"(xx), "l"((unsigned long long)w1.x));
                asm("fma.rn.f32x2 %0, %1, %2, %0;" : "+l"(acc[i][3]) : "l"(xx), "l"((unsigned long long)w1.y));
            }
        }
        __syncthreads();
    }

    const float4* as4 = (const float4*)asv;
    const float4* ad4 = (const float4*)adv;
    float4 sa0 = as4[ct * 2], sa1 = as4[ct * 2 + 1];
    float4 da0 = ad4[ct * 2], da1 = ad4[ct * 2 + 1];

    #pragma unroll
    for (int i = 0; i < 8; i++) {
        int row = row0 + r0 + i;
        float o[8];
        #pragma unroll
        for (int j = 0; j < 4; j++) {
            unsigned int lo, hi;
            asm("mov.b64 {%0, %1}, %2;" : "=r"(lo), "=r"(hi) : "l"(acc[i][j]));
            o[2 * j]     = __uint_as_float(lo);
            o[2 * j + 1] = __uint_as_float(hi);
        }
        float ps = o[0]*sa0.x + o[1]*sa0.y + o[2]*sa0.z + o[3]*sa0.w
                 + o[4]*sa1.x + o[5]*sa1.y + o[6]*sa1.z + o[7]*sa1.w;
        float pd = o[0]*da0.x + o[1]*da0.y + o[2]*da0.z + o[3]*da0.w
                 + o[4]*da1.x + o[5]*da1.y + o[6]*da1.z + o[7]*da1.w;
        #pragma unroll
        for (int m = 1; m < 8; m <<= 1) {
            ps += __shfl_xor_sync(0xffffffffu, ps, m);
            pd += __shfl_xor_sync(0xffffffffu, pd, m);
        }
        if (row < Nn) {
            __half2 p0 = __floats2half2_rn(o[0], o[1]);
            __half2 p1 = __floats2half2_rn(o[2], o[3]);
            __half2 p2 = __floats2half2_rn(o[4], o[5]);
            __half2 p3 = __floats2half2_rn(o[6], o[7]);
            uint4 pk;
            pk.x = *(unsigned int*)&p0; pk.y = *(unsigned int*)&p1;
            pk.z = *(unsigned int*)&p2; pk.w = *(unsigned int*)&p3;
            *(uint4*)(h + (size_t)row * 64 + ct * 8) = pk;
            if (ct == 0) { as_[row] = ps; ad_[row] = pd; }
        }
    }
}

// ---------------------------------------------------------------------------
// GEMM2: h2 = h1r @ W2 (K=64, C=40), fp16 output, alpha dots fused.
// ---------------------------------------------------------------------------
__global__ void gemm2_kernel(const float* __restrict__ x,
                             const float* __restrict__ W,
                             const float* __restrict__ asv,
                             const float* __restrict__ adv,
                             __half* __restrict__ h,
                             float* __restrict__ as_, float* __restrict__ ad_,
                             int Nn) {
    __shared__ float Xs[32][64];
    __shared__ float Ws[64][40];
    int tid = threadIdx.x;
    int row0 = blockIdx.x * 32;

    #pragma unroll
    for (int i = tid; i < 64 * 40; i += 128) Ws[i / 40][i % 40] = W[i];

    const float4* x4 = (const float4*)x;
    float4* Xs4 = (float4*)Xs;
    #pragma unroll
    for (int i = tid; i < 32 * 16; i += 128) {
        long long gi = (long long)row0 * 16 + i;
        Xs4[i] = (gi < (long long)Nn * 16) ? x4[gi] : make_float4(0.f, 0.f, 0.f, 0.f);
    }
    __syncthreads();

    int r0 = (tid >> 3) * 2;
    int c0 = (tid & 7) * 5;
    float acc[2][5] = {};
    #pragma unroll 4
    for (int k = 0; k < 64; k++) {
        float xv0 = Xs[r0][k];
        float xv1 = Xs[r0 + 1][k];
        #pragma unroll
        for (int j = 0; j < 5; j++) {
            float wv = Ws[k][c0 + j];
            acc[0][j] += xv0 * wv;
            acc[1][j] += xv1 * wv;
        }
    }

    float sa[5], da[5];
    #pragma unroll
    for (int j = 0; j < 5; j++) { sa[j] = asv[c0 + j]; da[j] = adv[c0 + j]; }

    #pragma unroll
    for (int i = 0; i < 2; i++) {
        int row = row0 + r0 + i;
        float ps = 0.f, pd = 0.f;
        #pragma unroll
        for (int j = 0; j < 5; j++) {
            ps += acc[i][j] * sa[j];
            pd += acc[i][j] * da[j];
        }
        #pragma unroll
        for (int m = 1; m < 8; m <<= 1) {
            ps += __shfl_xor_sync(0xffffffffu, ps, m);
            pd += __shfl_xor_sync(0xffffffffu, pd, m);
        }
        if (row < Nn) {
            __half* dstp = h + (size_t)row * 40 + c0;
            #pragma unroll
            for (int j = 0; j < 5; j++) dstp[j] = __float2half_rn(acc[i][j]);
            if ((tid & 7) == 0) { as_[row] = ps; ad_[row] = pd; }
        }
    }
}

// ---------------------------------------------------------------------------
// Fused GAT aggregation, one warp per destination (CSR), fp16 feature rows.
// Pass 2 accumulates each 16-edge chunk (4 edges per 8-lane subwarp) in
// __half2 HFMA2 registers, converting to fp32 once per chunk (halves the
// dominant cvt+fma instruction stream of this issue-bound kernel).
// rden applied once after the subwarp combine.
// ---------------------------------------------------------------------------
template <int F, bool FINAL>
__global__ void gat_agg_kernel(const int* __restrict__ srcs,
                               const int* __restrict__ off,
                               const float* __restrict__ as_,
                               const float* __restrict__ ad_,
                               const __half* __restrict__ h,
                               const float* __restrict__ bias,
                               float* __restrict__ outp, int Nn) {
    constexpr int LROW = F / 8;
    __shared__ float exco[8][96];
    __shared__ int   sso[8][96];
    int w = threadIdx.x >> 5, lane = threadIdx.x & 31;
    int d = blockIdx.x * 8 + w;
    if (d >= Nn) return;
    int beg = off[d], end = off[d + 1];
    int deg = end - beg;
    float advv = ad_[d];
    float* exc = exco[w];
    int*   ssc = sso[w];
    bool fits = (deg <= 96);

    // Pass 1: exp numerators + sum
    float sum = 0.f;
    for (int i = lane; i < deg; i += 32) {
        int s = srcs[beg + i];
        float e = as_[s] + advv;
        e = (e > 0.f) ? e : 0.2f * e;
        float xv = __expf(e);
        if (fits) { exc[i] = xv; ssc[i] = s; }
        sum += xv;
    }
    #pragma unroll
    for (int m = 16; m; m >>= 1) sum += __shfl_xor_sync(0xffffffffu, sum, m);
    float rden = 1.0f / sum;
    __syncwarp();

    int g = lane >> 3, l8 = lane & 7;
    bool act = (l8 < LROW);
    float a[8] = {0.f, 0.f, 0.f, 0.f, 0.f, 0.f, 0.f, 0.f};
    const float4* h4 = (const float4*)h;

    if (fits) {
        for (int it = 0; it < deg; it += 16) {
            __half2 hacc0 = __float2half2_rn(0.f);
            __half2 hacc1 = hacc0, hacc2 = hacc0, hacc3 = hacc0;
            #pragma unroll
            for (int q = 0; q < 4; q++) {
                int e = it + q * 4 + g;
                int idx = min(e, deg - 1);
                int s = ssc[idx];
                float cf = (e < deg) ? exc[idx] : 0.f;
                __half2 c2 = __float2half2_rn(cf);
                if (act) {
                    float4 v = __ldg(&h4[s * LROW + l8]);
                    const __half2* hp = (const __half2*)&v;
                    hacc0 = __hfma2(hp[0], c2, hacc0);
                    hacc1 = __hfma2(hp[1], c2, hacc1);
                    hacc2 = __hfma2(hp[2], c2, hacc2);
                    hacc3 = __hfma2(hp[3], c2, hacc3);
                }
            }
            float2 f0 = __half22float2(hacc0);
            float2 f1 = __half22float2(hacc1);
            float2 f2 = __half22float2(hacc2);
            float2 f3 = __half22float2(hacc3);
            a[0] += f0.x; a[1] += f0.y; a[2] += f1.x; a[3] += f1.y;
            a[4] += f2.x; a[5] += f2.y; a[6] += f3.x; a[7] += f3.y;
        }
    } else {
        for (int it = 0; it < deg; it += 4) {
            int e = it + g;
            if (e < deg) {
                int s = srcs[beg + e];
                float ev = as_[s] + advv;
                ev = (ev > 0.f) ? ev : 0.2f * ev;
                float c = __expf(ev);
                if (act) {
                    float4 v = __ldg(&h4[s * LROW + l8]);
                    const __half2* hp = (const __half2*)&v;
                    float2 f0 = __half22float2(hp[0]);
                    float2 f1 = __half22float2(hp[1]);
                    float2 f2 = __half22float2(hp[2]);
                    float2 f3 = __half22float2(hp[3]);
                    a[0] = fmaf(f0.x, c, a[0]); a[1] = fmaf(f0.y, c, a[1]);
                    a[2] = fmaf(f1.x, c, a[2]); a[3] = fmaf(f1.y, c, a[3]);
                    a[4] = fmaf(f2.x, c, a[4]); a[5] = fmaf(f2.y, c, a[5]);
                    a[6] = fmaf(f3.x, c, a[6]); a[7] = fmaf(f3.y, c, a[7]);
                }
            }
        }
    }

    // Combine the 4 subwarps, then apply 1/den once.
    #pragma unroll
    for (int m = 8; m < 32; m <<= 1)
        #pragma unroll
        for (int j = 0; j < 8; j++)
            a[j] += __shfl_xor_sync(0xffffffffu, a[j], m);
    #pragma unroll
    for (int j = 0; j < 8; j++) a[j] *= rden;

    if (!FINAL) {
        if (lane < LROW) {
            float o[8];
            #pragma unroll
            for (int j = 0; j < 8; j++)
                o[j] = fmaxf(a[j] + bias[l8 * 8 + j], 0.f);
            float* dstp = outp + (size_t)d * F + l8 * 8;
            *(float4*)dstp       = make_float4(o[0], o[1], o[2], o[3]);
            *(float4*)(dstp + 4) = make_float4(o[4], o[5], o[6], o[7]);
        }
    } else {
        float v[8];
        float mx = __int_as_float(0xff800000);
        if (act) {
            #pragma unroll
            for (int j = 0; j < 8; j++) {
                v[j] = a[j] + bias[l8 * 8 + j];
                mx = fmaxf(mx, v[j]);
            }
        }
        #pragma unroll
        for (int m = 1; m < 8; m <<= 1) mx = fmaxf(mx, __shfl_xor_sync(0xffffffffu, mx, m));
        float se = 0.f;
        if (act) {
            #pragma unroll
            for (int j = 0; j < 8; j++) se += __expf(v[j] - mx);
        }
        #pragma unroll
        for (int m = 1; m < 8; m <<= 1) se += __shfl_xor_sync(0xffffffffu, se, m);
        float ls = mx + __logf(se);
        if (lane < LROW) {
            float* dstp = outp + (size_t)d * F + l8 * 8;
            *(float4*)dstp       = make_float4(v[0] - ls, v[1] - ls, v[2] - ls, v[3] - ls);
            *(float4*)(dstp + 4) = make_float4(v[4] - ls, v[5] - ls, v[6] - ls, v[7] - ls);
        }
    }
}

// ---------------------------------------------------------------------------
// Launch: CSR build on side stream, overlapped with gemm1.
// ---------------------------------------------------------------------------
extern "C" void kernel_launch(void* const* d_in, const int* in_sizes, int n_in,
                              void* d_out, int out_size) {
    const float* x       = (const float*)d_in[0];
    const unsigned int* ei_raw = (const unsigned int*)d_in[1];
    const float* W1      = (const float*)d_in[2];
    const float* a_src1  = (const float*)d_in[3];
    const float* a_dst1  = (const float*)d_in[4];
    const float* b1      = (const float*)d_in[5];
    const float* W2      = (const float*)d_in[6];
    const float* a_src2  = (const float*)d_in[7];
    const float* a_dst2  = (const float*)d_in[8];
    const float* b2      = (const float*)d_in[9];
    float* out           = (float*)d_out;

    int Nn = in_sizes[0] / 128;
    long long E = in_sizes[1] / 2;
    long long T = E + Nn;

    float *p_h1r, *p_as, *p_ad;
    __half *p_h1h, *p_h2h;
    int *p_cnt, *p_off, *p_srcs, *p_rank, *p_part, *p_bar, *p_is64;
    cudaGetSymbolAddress((void**)&p_h1h, g_h1h);
    cudaGetSymbolAddress((void**)&p_h1r, g_h1r);
    cudaGetSymbolAddress((void**)&p_h2h, g_h2h);
    cudaGetSymbolAddress((void**)&p_as, g_as);
    cudaGetSymbolAddress((void**)&p_ad, g_ad);
    cudaGetSymbolAddress((void**)&p_cnt, g_cnt);
    cudaGetSymbolAddress((void**)&p_off, g_off);
    cudaGetSymbolAddress((void**)&p_srcs, g_srcs);
    cudaGetSymbolAddress((void**)&p_rank, g_rank);
    cudaGetSymbolAddress((void**)&p_part, g_partials);
    cudaGetSymbolAddress((void**)&p_bar, g_barrier);
    cudaGetSymbolAddress((void**)&p_is64, g_is64);

    static cudaStream_t s2 = nullptr;
    static cudaEvent_t evF = nullptr, evC = nullptr;
    if (!s2) {
        cudaStreamCreateWithFlags(&s2, cudaStreamNonBlocking);
        cudaEventCreateWithFlags(&evF, cudaEventDisableTiming);
        cudaEventCreateWithFlags(&evC, cudaEventDisableTiming);
    }

    const int TB = 256;
    int nb = (Nn + 1023) / 1024;   // 98

    // ---- Fork: CSR build on s2, gemm1 on main stream ----
    cudaEventRecord(evF, 0);
    cudaStreamWaitEvent(s2, evF, 0);

    init_detect_kernel<<<392, 256, 0, s2>>>(ei_raw, p_cnt, p_is64, p_bar, Nn);
    hist_kernel<<<(int)((E + TB - 1) / TB), TB, 0, s2>>>(ei_raw, p_cnt, p_rank, E, p_is64);
    scan_kernel<<<nb, 1024, 0, s2>>>(p_cnt, p_off, p_part, p_bar, Nn, (int)T);
    fill_kernel<<<(int)((T + TB - 1) / TB), TB, 0, s2>>>(ei_raw, p_off, p_cnt, p_rank, p_srcs, E, T, p_is64);
    cudaEventRecord(evC, s2);

    gemm1_kernel<<<(Nn + 127) / 128, 128>>>(x, W1, a_src1, a_dst1, p_h1h, p_as, p_ad, Nn);

    // ---- Join ----
    cudaStreamWaitEvent(0, evC, 0);
    gat_agg_kernel<64, false><<<(Nn + 7) / 8, 256>>>(p_srcs, p_off, p_as, p_ad, p_h1h, b1, p_h1r, Nn);
    gemm2_kernel<<<(Nn + 31) / 32, 128>>>(p_h1r, W2, a_src2, a_dst2, p_h2h, p_as, p_ad, Nn);
    gat_agg_kernel<40, true><<<(Nn + 7) / 8, 256>>>(p_srcs, p_off, p_as, p_ad, p_h2h, b2, out, Nn);
}

// round 15
// speedup vs baseline: 1.3356x; 1.0469x over previous
#include <cuda_runtime.h>
#include <cuda_fp16.h>
#include <math.h>

// ---------------------------------------------------------------------------
// N=100000, F_in=128, F_hid=64, F_out=40, E=1600000 (+N self loops).
// h1 / h2 stored fp16; fp32 accumulation everywhere.
// ---------------------------------------------------------------------------
#define MAXN 100000
#define MAXE 1700096

__device__ __half g_h1h[(size_t)MAXN * 64];
__device__ float  g_h1r[(size_t)MAXN * 64];
__device__ __half g_h2h[(size_t)MAXN * 40];
__device__ float  g_as[MAXN];
__device__ float  g_ad[MAXN];
__device__ int    g_cnt[MAXN];
__device__ int    g_off[MAXN + 1];
__device__ int    g_srcs[MAXE];
__device__ int    g_rank[MAXE];
__device__ int    g_partials[128];
__device__ int    g_barrier;
__device__ int    g_is64;

// ---------------------------------------------------------------------------
// Init + dtype detect
// ---------------------------------------------------------------------------
__global__ void init_detect_kernel(const unsigned int* __restrict__ w,
                                   int* __restrict__ cnt, int* flag,
                                   int* barrier, int n) {
    int i = blockIdx.x * blockDim.x + threadIdx.x;
    int stride = gridDim.x * blockDim.x;
    for (int j = i; j < n; j += stride) cnt[j] = 0;
    if (blockIdx.x == 0) {
        __shared__ int any;
        if (threadIdx.x == 0) { any = 0; *barrier = 0; }
        __syncthreads();
        for (int k = threadIdx.x; k < 1024; k += blockDim.x)
            if (w[2 * k + 1] != 0u) atomicOr(&any, 1);
        __syncthreads();
        if (threadIdx.x == 0) *flag = any ? 0 : 1;  // 1 => int64
    }
}

// ---------------------------------------------------------------------------
// Hist: count destinations AND record each edge's rank within its dst.
// ---------------------------------------------------------------------------
__global__ void hist_kernel(const unsigned int* __restrict__ w,
                            int* __restrict__ cnt, int* __restrict__ rank,
                            long long E, const int* __restrict__ flag) {
    long long i = (long long)blockIdx.x * blockDim.x + threadIdx.x;
    if (i >= E) return;
    int is64 = *flag;
    int d = is64 ? (int)((const uint2*)w)[E + i].x : (int)w[E + i];
    rank[i] = atomicAdd(&cnt[d], 1);
}

// ---------------------------------------------------------------------------
// One-kernel exclusive scan of (cnt[i]+1) -> off.
// ---------------------------------------------------------------------------
__global__ void scan_kernel(const int* __restrict__ cnt,
                            int* __restrict__ off,
                            int* __restrict__ partials, int* __restrict__ barrier,
                            int n, int total) {
    __shared__ int sm[1024];
    __shared__ int pf[128];
    int tid = threadIdx.x, b = blockIdx.x;
    int i = b * 1024 + tid;
    int v = (i < n) ? cnt[i] + 1 : 0;   // +1 = self loop
    sm[tid] = v;
    __syncthreads();
    #pragma unroll
    for (int o = 1; o < 1024; o <<= 1) {
        int t = (tid >= o) ? sm[tid - o] : 0;
        __syncthreads();
        sm[tid] += t;
        __syncthreads();
    }
    int incl = sm[tid];

    if (tid == 0) {
        partials[b] = sm[1023];
        __threadfence();
        atomicAdd(barrier, 1);
        while (atomicAdd(barrier, 0) < gridDim.x) {}
    }
    __syncthreads();

    pf[tid & 127] = 0;
    __syncthreads();
    if (tid < 128) pf[tid] = (tid < b) ? partials[tid] : 0;
    __syncthreads();
    #pragma unroll
    for (int o = 64; o; o >>= 1) {
        if (tid < o) pf[tid] += pf[tid + o];
        __syncthreads();
    }
    int prefix = pf[0];

    if (i < n) off[i] = prefix + incl - v;
    if (i == 0) off[n] = total;
}

// ---------------------------------------------------------------------------
// Fill: atomic-free scatter using precomputed ranks.
// ---------------------------------------------------------------------------
__global__ void fill_kernel(const unsigned int* __restrict__ w,
                            const int* __restrict__ off,
                            const int* __restrict__ cnt,
                            const int* __restrict__ rank,
                            int* __restrict__ srcs,
                            long long E, long long T,
                            const int* __restrict__ flag) {
    long long t = (long long)blockIdx.x * blockDim.x + threadIdx.x;
    if (t >= T) return;
    int is64 = *flag;
    if (t < E) {
        int s, d;
        if (is64) {
            const uint2* w2 = (const uint2*)w;
            s = (int)w2[t].x;
            d = (int)w2[E + t].x;
        } else {
            s = (int)w[t];
            d = (int)w[E + t];
        }
        srcs[off[d] + rank[t]] = s;
    } else {
        int d = (int)(t - E);
        srcs[off[d] + cnt[d]] = d;
    }
}

// ---------------------------------------------------------------------------
// GEMM1: h = x @ W (K=128, C=64), fp32 accumulation, fp16 output rows.
// Alpha dots fused into epilogue.
// ---------------------------------------------------------------------------
__global__ void gemm1_kernel(const float* __restrict__ x,
                             const float* __restrict__ W,
                             const float* __restrict__ asv,
                             const float* __restrict__ adv,
                             __half* __restrict__ h,
                             float* __restrict__ as_, float* __restrict__ ad_,
                             int Nn) {
    __shared__ float Xs[128 * 32];
    __shared__ float Ws[32 * 64];
    int tid = threadIdx.x;
    int row0 = blockIdx.x * 128;
    int rt = tid >> 3;
    int ct = tid & 7;
    int r0 = rt * 8;
    int kx = (rt & 3) << 3;

    unsigned long long acc[8][4];
    #pragma unroll
    for (int i = 0; i < 8; i++)
        #pragma unroll
        for (int j = 0; j < 4; j++) acc[i][j] = 0ull;

    const float4* x4 = (const float4*)x;

    for (int kc = 0; kc < 4; kc++) {
        const float4* W4 = (const float4*)(W + kc * 32 * 64);
        #pragma unroll
        for (int i = tid; i < 512; i += 128) ((float4*)Ws)[i] = W4[i];
        #pragma unroll
        for (int i = tid; i < 1024; i += 128) {
            int row = i >> 3;
            int c4  = i & 7;
            int gr = row0 + row;
            float4 v = (gr < Nn) ? x4[(size_t)gr * 32 + kc * 8 + c4]
                                 : make_float4(0.f, 0.f, 0.f, 0.f);
            int col = (c4 * 4) ^ (((row >> 3) & 3) << 3);
            *(float4*)&Xs[row * 32 + col] = v;
        }
        __syncthreads();

        #pragma unroll
        for (int k = 0; k < 32; k++) {
            longlong2 w0 = *(const longlong2*)&Ws[k * 64 + ct * 8];
            longlong2 w1 = *(const longlong2*)&Ws[k * 64 + ct * 8 + 4];
            #pragma unroll
            for (int i = 0; i < 8; i++) {
                float xv = Xs[(r0 + i) * 32 + (k ^ kx)];
                unsigned long long xx;
                asm("mov.b64 %0, {%1, %1};" : "=l"(xx) : "r"(__float_as_uint(xv)));
                asm("fma.rn.f32x2 %0, %1, %2, %0;" : "+l"(acc[i][0]) : "l"(xx), "l"((unsigned long long)w0.x));
                asm("fma.rn.f32x2 %0, %1, %2, %0;" : "+l"(acc[i][1]) : "l"(xx), "l"((unsigned long long)w0.y));
                asm("fma.rn.f32x2 %0, %1, %2, %0;" : "+l"(acc[i][2]) : "l"(xx), "l"((unsigned long long)w1.x));
                asm("fma.rn.f32x2 %0, %1, %2, %0;" : "+l"(acc[i][3]) : "l"(xx), "l"((unsigned long long)w1.y));
            }
        }
        __syncthreads();
    }

    const float4* as4 = (const float4*)asv;
    const float4* ad4 = (const float4*)adv;
    float4 sa0 = as4[ct * 2], sa1 = as4[ct * 2 + 1];
    float4 da0 = ad4[ct * 2], da1 = ad4[ct * 2 + 1];

    #pragma unroll
    for (int i = 0; i < 8; i++) {
        int row = row0 + r0 + i;
        float o[8];
        #pragma unroll
        for (int j = 0; j < 4; j++) {
            unsigned int lo, hi;
            asm("mov.b64 {%0, %1}, %2;" : "=r"(lo), "=r"(hi) : "l"(acc[i][j]));
            o[2 * j]     = __uint_as_float(lo);
            o[2 * j + 1] = __uint_as_float(hi);
        }
        float ps = o[0]*sa0.x + o[1]*sa0.y + o[2]*sa0.z + o[3]*sa0.w
                 + o[4]*sa1.x + o[5]*sa1.y + o[6]*sa1.z + o[7]*sa1.w;
        float pd = o[0]*da0.x + o[1]*da0.y + o[2]*da0.z + o[3]*da0.w
                 + o[4]*da1.x + o[5]*da1.y + o[6]*da1.z + o[7]*da1.w;
        #pragma unroll
        for (int m = 1; m < 8; m <<= 1) {
            ps += __shfl_xor_sync(0xffffffffu, ps, m);
            pd += __shfl_xor_sync(0xffffffffu, pd, m);
        }
        if (row < Nn) {
            __half2 p0 = __floats2half2_rn(o[0], o[1]);
            __half2 p1 = __floats2half2_rn(o[2], o[3]);
            __half2 p2 = __floats2half2_rn(o[4], o[5]);
            __half2 p3 = __floats2half2_rn(o[6], o[7]);
            uint4 pk;
            pk.x = *(unsigned int*)&p0; pk.y = *(unsigned int*)&p1;
            pk.z = *(unsigned int*)&p2; pk.w = *(unsigned int*)&p3;
            *(uint4*)(h + (size_t)row * 64 + ct * 8) = pk;
            if (ct == 0) { as_[row] = ps; ad_[row] = pd; }
        }
    }
}

// ---------------------------------------------------------------------------
// GEMM2: h2 = h1r @ W2 (K=64, C=40), fp16 output, alpha dots fused.
// ---------------------------------------------------------------------------
__global__ void gemm2_kernel(const float* __restrict__ x,
                             const float* __restrict__ W,
                             const float* __restrict__ asv,
                             const float* __restrict__ adv,
                             __half* __restrict__ h,
                             float* __restrict__ as_, float* __restrict__ ad_,
                             int Nn) {
    __shared__ float Xs[32][64];
    __shared__ float Ws[64][40];
    int tid = threadIdx.x;
    int row0 = blockIdx.x * 32;

    #pragma unroll
    for (int i = tid; i < 64 * 40; i += 128) Ws[i / 40][i % 40] = W[i];

    const float4* x4 = (const float4*)x;
    float4* Xs4 = (float4*)Xs;
    #pragma unroll
    for (int i = tid; i < 32 * 16; i += 128) {
        long long gi = (long long)row0 * 16 + i;
        Xs4[i] = (gi < (long long)Nn * 16) ? x4[gi] : make_float4(0.f, 0.f, 0.f, 0.f);
    }
    __syncthreads();

    int r0 = (tid >> 3) * 2;
    int c0 = (tid & 7) * 5;
    float acc[2][5] = {};
    #pragma unroll 4
    for (int k = 0; k < 64; k++) {
        float xv0 = Xs[r0][k];
        float xv1 = Xs[r0 + 1][k];
        #pragma unroll
        for (int j = 0; j < 5; j++) {
            float wv = Ws[k][c0 + j];
            acc[0][j] += xv0 * wv;
            acc[1][j] += xv1 * wv;
        }
    }

    float sa[5], da[5];
    #pragma unroll
    for (int j = 0; j < 5; j++) { sa[j] = asv[c0 + j]; da[j] = adv[c0 + j]; }

    #pragma unroll
    for (int i = 0; i < 2; i++) {
        int row = row0 + r0 + i;
        float ps = 0.f, pd = 0.f;
        #pragma unroll
        for (int j = 0; j < 5; j++) {
            ps += acc[i][j] * sa[j];
            pd += acc[i][j] * da[j];
        }
        #pragma unroll
        for (int m = 1; m < 8; m <<= 1) {
            ps += __shfl_xor_sync(0xffffffffu, ps, m);
            pd += __shfl_xor_sync(0xffffffffu, pd, m);
        }
        if (row < Nn) {
            __half* dstp = h + (size_t)row * 40 + c0;
            #pragma unroll
            for (int j = 0; j < 5; j++) dstp[j] = __float2half_rn(acc[i][j]);
            if ((tid & 7) == 0) { as_[row] = ps; ad_[row] = pd; }
        }
    }
}

// ---------------------------------------------------------------------------
// Fused GAT aggregation, one warp per destination (CSR), fp16 feature rows.
// PADDING-OPTIMIZED: deg<=16 takes a single unrolled clamped chunk (47% of
// Poisson(17) nodes); looped path uses 8-edge chunks (2 per subwarp) to cut
// padded-edge waste from ~46% to ~24%. rden applied once post-combine.
// ---------------------------------------------------------------------------
template <int F, bool FINAL>
__global__ void gat_agg_kernel(const int* __restrict__ srcs,
                               const int* __restrict__ off,
                               const float* __restrict__ as_,
                               const float* __restrict__ ad_,
                               const __half* __restrict__ h,
                               const float* __restrict__ bias,
                               float* __restrict__ outp, int Nn) {
    constexpr int LROW = F / 8;
    __shared__ float exco[8][96];
    __shared__ int   sso[8][96];
    int w = threadIdx.x >> 5, lane = threadIdx.x & 31;
    int d = blockIdx.x * 8 + w;
    if (d >= Nn) return;
    int beg = off[d], end = off[d + 1];
    int deg = end - beg;
    float advv = ad_[d];
    float* exc = exco[w];
    int*   ssc = sso[w];
    bool fits = (deg <= 96);

    // Pass 1: exp numerators + sum (coefs+indices cached in smem)
    float sum = 0.f;
    for (int i = lane; i < deg; i += 32) {
        int s = srcs[beg + i];
        float e = as_[s] + advv;
        e = (e > 0.f) ? e : 0.2f * e;
        float xv = __expf(e);
        if (fits) { exc[i] = xv; ssc[i] = s; }
        sum += xv;
    }
    #pragma unroll
    for (int m = 16; m; m >>= 1) sum += __shfl_xor_sync(0xffffffffu, sum, m);
    float rden = 1.0f / sum;
    __syncwarp();

    int g = lane >> 3, l8 = lane & 7;
    const bool act = (F == 64) || (l8 < LROW);
    float a[8] = {0.f, 0.f, 0.f, 0.f, 0.f, 0.f, 0.f, 0.f};
    const float4* h4 = (const float4*)h;

    #define ACC8(vv, cc) { \
        const __half2* hp = (const __half2*)&(vv); \
        float2 f0 = __half22float2(hp[0]); \
        float2 f1 = __half22float2(hp[1]); \
        float2 f2 = __half22float2(hp[2]); \
        float2 f3 = __half22float2(hp[3]); \
        a[0] = fmaf(f0.x, (cc), a[0]); a[1] = fmaf(f0.y, (cc), a[1]); \
        a[2] = fmaf(f1.x, (cc), a[2]); a[3] = fmaf(f1.y, (cc), a[3]); \
        a[4] = fmaf(f2.x, (cc), a[4]); a[5] = fmaf(f2.y, (cc), a[5]); \
        a[6] = fmaf(f3.x, (cc), a[6]); a[7] = fmaf(f3.y, (cc), a[7]); }

    if (deg <= 16) {
        // single clamped chunk: 4 edges per subwarp, fully unrolled
        #pragma unroll
        for (int q = 0; q < 4; q++) {
            int e = q * 4 + g;
            int idx = min(e, deg - 1);
            int s = ssc[idx];
            float c = (e < deg) ? exc[idx] : 0.f;
            if (act) {
                float4 v = __ldg(&h4[s * LROW + l8]);
                ACC8(v, c)
            }
        }
    } else if (fits) {
        // 8-edge chunks: 2 edges per subwarp per iteration, branchless clamp
        for (int it = 0; it < deg; it += 8) {
            int e0 = it + g, e1 = it + 4 + g;
            int i0 = min(e0, deg - 1), i1 = min(e1, deg - 1);
            int s0 = ssc[i0], s1 = ssc[i1];
            float c0 = (e0 < deg) ? exc[i0] : 0.f;
            float c1 = (e1 < deg) ? exc[i1] : 0.f;
            if (act) {
                float4 v0 = __ldg(&h4[s0 * LROW + l8]);
                float4 v1 = __ldg(&h4[s1 * LROW + l8]);
                ACC8(v0, c0)
                ACC8(v1, c1)
            }
        }
    } else {
        for (int it = 0; it < deg; it += 4) {
            int e = it + g;
            if (e < deg) {
                int s = srcs[beg + e];
                float ev = as_[s] + advv;
                ev = (ev > 0.f) ? ev : 0.2f * ev;
                float c = __expf(ev);
                if (act) {
                    float4 v = __ldg(&h4[s * LROW + l8]);
                    ACC8(v, c)
                }
            }
        }
    }
    #undef ACC8

    // Combine the 4 subwarps, then apply 1/den once.
    #pragma unroll
    for (int m = 8; m < 32; m <<= 1)
        #pragma unroll
        for (int j = 0; j < 8; j++)
            a[j] += __shfl_xor_sync(0xffffffffu, a[j], m);
    #pragma unroll
    for (int j = 0; j < 8; j++) a[j] *= rden;

    if (!FINAL) {
        if (lane < LROW) {
            float o[8];
            #pragma unroll
            for (int j = 0; j < 8; j++)
                o[j] = fmaxf(a[j] + bias[l8 * 8 + j], 0.f);
            float* dstp = outp + (size_t)d * F + l8 * 8;
            *(float4*)dstp       = make_float4(o[0], o[1], o[2], o[3]);
            *(float4*)(dstp + 4) = make_float4(o[4], o[5], o[6], o[7]);
        }
    } else {
        float v[8];
        float mx = __int_as_float(0xff800000);
        if (act) {
            #pragma unroll
            for (int j = 0; j < 8; j++) {
                v[j] = a[j] + bias[l8 * 8 + j];
                mx = fmaxf(mx, v[j]);
            }
        }
        #pragma unroll
        for (int m = 1; m < 8; m <<= 1) mx = fmaxf(mx, __shfl_xor_sync(0xffffffffu, mx, m));
        float se = 0.f;
        if (act) {
            #pragma unroll
            for (int j = 0; j < 8; j++) se += __expf(v[j] - mx);
        }
        #pragma unroll
        for (int m = 1; m < 8; m <<= 1) se += __shfl_xor_sync(0xffffffffu, se, m);
        float ls = mx + __logf(se);
        if (lane < LROW) {
            float* dstp = outp + (size_t)d * F + l8 * 8;
            *(float4*)dstp       = make_float4(v[0] - ls, v[1] - ls, v[2] - ls, v[3] - ls);
            *(float4*)(dstp + 4) = make_float4(v[4] - ls, v[5] - ls, v[6] - ls, v[7] - ls);
        }
    }
}

// ---------------------------------------------------------------------------
// Launch: CSR build on side stream, overlapped with gemm1.
// ---------------------------------------------------------------------------
extern "C" void kernel_launch(void* const* d_in, const int* in_sizes, int n_in,
                              void* d_out, int out_size) {
    const float* x       = (const float*)d_in[0];
    const unsigned int* ei_raw = (const unsigned int*)d_in[1];
    const float* W1      = (const float*)d_in[2];
    const float* a_src1  = (const float*)d_in[3];
    const float* a_dst1  = (const float*)d_in[4];
    const float* b1      = (const float*)d_in[5];
    const float* W2      = (const float*)d_in[6];
    const float* a_src2  = (const float*)d_in[7];
    const float* a_dst2  = (const float*)d_in[8];
    const float* b2      = (const float*)d_in[9];
    float* out           = (float*)d_out;

    int Nn = in_sizes[0] / 128;
    long long E = in_sizes[1] / 2;
    long long T = E + Nn;

    float *p_h1r, *p_as, *p_ad;
    __half *p_h1h, *p_h2h;
    int *p_cnt, *p_off, *p_srcs, *p_rank, *p_part, *p_bar, *p_is64;
    cudaGetSymbolAddress((void**)&p_h1h, g_h1h);
    cudaGetSymbolAddress((void**)&p_h1r, g_h1r);
    cudaGetSymbolAddress((void**)&p_h2h, g_h2h);
    cudaGetSymbolAddress((void**)&p_as, g_as);
    cudaGetSymbolAddress((void**)&p_ad, g_ad);
    cudaGetSymbolAddress((void**)&p_cnt, g_cnt);
    cudaGetSymbolAddress((void**)&p_off, g_off);
    cudaGetSymbolAddress((void**)&p_srcs, g_srcs);
    cudaGetSymbolAddress((void**)&p_rank, g_rank);
    cudaGetSymbolAddress((void**)&p_part, g_partials);
    cudaGetSymbolAddress((void**)&p_bar, g_barrier);
    cudaGetSymbolAddress((void**)&p_is64, g_is64);

    static cudaStream_t s2 = nullptr;
    static cudaEvent_t evF = nullptr, evC = nullptr;
    if (!s2) {
        cudaStreamCreateWithFlags(&s2, cudaStreamNonBlocking);
        cudaEventCreateWithFlags(&evF, cudaEventDisableTiming);
        cudaEventCreateWithFlags(&evC, cudaEventDisableTiming);
    }

    const int TB = 256;
    int nb = (Nn + 1023) / 1024;   // 98

    // ---- Fork: CSR build on s2, gemm1 on main stream ----
    cudaEventRecord(evF, 0);
    cudaStreamWaitEvent(s2, evF, 0);

    init_detect_kernel<<<392, 256, 0, s2>>>(ei_raw, p_cnt, p_is64, p_bar, Nn);
    hist_kernel<<<(int)((E + TB - 1) / TB), TB, 0, s2>>>(ei_raw, p_cnt, p_rank, E, p_is64);
    scan_kernel<<<nb, 1024, 0, s2>>>(p_cnt, p_off, p_part, p_bar, Nn, (int)T);
    fill_kernel<<<(int)((T + TB - 1) / TB), TB, 0, s2>>>(ei_raw, p_off, p_cnt, p_rank, p_srcs, E, T, p_is64);
    cudaEventRecord(evC, s2);

    gemm1_kernel<<<(Nn + 127) / 128, 128>>>(x, W1, a_src1, a_dst1, p_h1h, p_as, p_ad, Nn);

    // ---- Join ----
    cudaStreamWaitEvent(0, evC, 0);
    gat_agg_kernel<64, false><<<(Nn + 7) / 8, 256>>>(p_srcs, p_off, p_as, p_ad, p_h1h, b1, p_h1r, Nn);
    gemm2_kernel<<<(Nn + 31) / 32, 128>>>(p_h1r, W2, a_src2, a_dst2, p_h2h, p_as, p_ad, Nn);
    gat_agg_kernel<40, true><<<(Nn + 7) / 8, 256>>>(p_srcs, p_off, p_as, p_ad, p_h2h, b2, out, Nn);
}